// round 14
// baseline (speedup 1.0000x reference)
#include <cuda_runtime.h>
#include <cuda_fp16.h>
#include <math.h>

// Problem constants (match reference)
#define NN   50000
#define EE   1600000
#define INC  64
#define HID  16
#define HEADS 8
#define C1   (HEADS * HID)  // 128
#define OUTC 32
#define BG   256
#define SLOPE 0.2f
#define SCAN_BLOCKS ((NN + 255) / 256)   // 196

// ---------------- scratch (device globals; no allocation allowed) ------------
__device__ __align__(16) __half g_xl1h[NN * C1];   // fp16 source-transform (layer 1)
__device__ __align__(16) float g_xr1[NN * C1];
__device__ __align__(16) __half g_xl2h[NN * HID];  // fp16 source-transform (layer 2)
__device__ __align__(16) float g_xr2[NN * HID];
__device__ __align__(16) float g_pool[BG * HID];
__device__ float g_cnt[BG];
// CSR scratch. g_count is ZERO at entry: zero-initialized at load, and tail-zeroed
// by zero_count at the end of every call (deterministic across replays).
__device__ int g_count[NN];
__device__ int g_cursor[NN];
__device__ int g_rowstart[NN + 1];
__device__ int g_srcs[EE];
__device__ int g_bsum[SCAN_BLOCKS];
__device__ int g_scanflag;        // reset by zero_count each call
__device__ unsigned g_ticket;     // reset by the last gat2 block each call

__device__ __forceinline__ float elu1(float v) { return v > 0.f ? v : (__expf(v) - 1.f); }
__device__ __forceinline__ float lrelu(float v) { return v > 0.f ? v : SLOPE * v; }

// ---------------- zero helpers ------------------------------------------------
__global__ void zero_poolcnt() {
    int i = blockIdx.x * blockDim.x + threadIdx.x;
    if (i < BG * HID) g_pool[i] = 0.f;
    if (i < BG) g_cnt[i] = 0.f;
}

__global__ void zero_count() {       // tail: reset histogram + scan flag for NEXT call
    int i = blockIdx.x * blockDim.x + threadIdx.x;
    if (i < NN) g_count[i] = 0;
    if (i == 0) g_scanflag = 0;
}

// ---------------- CSR build: histogram (4 edges/thread) ----------------------
__global__ void csr_hist(const int* __restrict__ ei) {
    int t = blockIdx.x * blockDim.x + threadIdx.x;
    if (t * 4 >= EE) return;
    int4 d = ((const int4*)(ei + EE))[t];
    atomicAdd(&g_count[d.x], 1);
    atomicAdd(&g_count[d.y], 1);
    atomicAdd(&g_count[d.z], 1);
    atomicAdd(&g_count[d.w], 1);
}

// ---------------- single-kernel scan (flag-synced two phases) ----------------
// 196 blocks all resident in wave 1 (far under occupancy limits) -> spin is safe.
__global__ void scan_fused() {
    __shared__ int sh[256];
    __shared__ int bs[256];
    int t = threadIdx.x, bid = blockIdx.x;
    int i = bid * 256 + t;
    int v = (i < NN) ? g_count[i] : 0;
    sh[t] = v;
    __syncthreads();
    for (int off = 1; off < 256; off <<= 1) {
        int u = (t >= off) ? sh[t - off] : 0;
        __syncthreads();
        sh[t] += u;
        __syncthreads();
    }
    if (t == 0) {
        g_bsum[bid] = sh[255];
        __threadfence();
        atomicAdd(&g_scanflag, 1);
        while (atomicAdd(&g_scanflag, 0) < SCAN_BLOCKS) { }   // wait for all blocks
    }
    __syncthreads();
    bs[t] = (t < SCAN_BLOCKS) ? g_bsum[t] : 0;
    __syncthreads();
    for (int off = 1; off < 256; off <<= 1) {
        int u = (t >= off) ? bs[t - off] : 0;
        __syncthreads();
        bs[t] += u;
        __syncthreads();
    }
    int blockpref = (bid == 0) ? 0 : bs[bid - 1];
    int excl = sh[t] - v + blockpref;
    if (i < NN) { g_rowstart[i] = excl; g_cursor[i] = excl; }
    if (i == NN - 1) g_rowstart[NN] = excl + v;
}

// ---------------- CSR fill (4 edges/thread, int4) ----------------------------
__global__ void csr_fill(const int* __restrict__ ei) {
    int t = blockIdx.x * blockDim.x + threadIdx.x;
    if (t * 4 >= EE) return;
    int4 s = ((const int4*)ei)[t];
    int4 d = ((const int4*)(ei + EE))[t];
    g_srcs[atomicAdd(&g_cursor[d.x], 1)] = s.x;
    g_srcs[atomicAdd(&g_cursor[d.y], 1)] = s.y;
    g_srcs[atomicAdd(&g_cursor[d.z], 1)] = s.z;
    g_srcs[atomicAdd(&g_cursor[d.w], 1)] = s.w;
}

// ---------------- layer 1: node transforms, 16 nodes per block ---------------
__global__ void transform1_tiled(const float* __restrict__ x,
                                 const float* __restrict__ wl, const float* __restrict__ bl,
                                 const float* __restrict__ wr, const float* __restrict__ br) {
    __shared__ float sx[16 * INC];
    int j = threadIdx.x;            // output channel 0..127
    int n0 = blockIdx.x * 16;
    const float* xb = x + n0 * INC;
#pragma unroll
    for (int i = 0; i < 8; i++) sx[j + i * 128] = xb[j + i * 128];
    __syncthreads();
    float blv = bl[j], brv = br[j];
    float sl[16], sr[16];
#pragma unroll
    for (int t = 0; t < 16; t++) { sl[t] = blv; sr[t] = brv; }
#pragma unroll 4
    for (int k = 0; k < INC; k++) {
        float wlv = wl[k * C1 + j];
        float wrv = wr[k * C1 + j];
#pragma unroll
        for (int t = 0; t < 16; t++) {
            float xv = sx[t * INC + k];
            sl[t] = fmaf(xv, wlv, sl[t]);
            sr[t] = fmaf(xv, wrv, sr[t]);
        }
    }
#pragma unroll
    for (int t = 0; t < 16; t++) {
        g_xl1h[(n0 + t) * C1 + j] = __float2half(sl[t]);
        g_xr1[(n0 + t) * C1 + j] = sr[t];
    }
}

// ---------------- fused layer-1 gather + layer-2 transform -------------------
// Phase A (per warp, node n): 2-slot x 16-lane gather (as R12), h1 -> smem.
// Phase B (block): xl2h/xr2 = h1 @ wl2/wr2 for the block's 8 nodes.
__global__ void gat1_fused(const float* __restrict__ att, const float* __restrict__ bias,
                           const float* __restrict__ wl2, const float* __restrict__ bl2,
                           const float* __restrict__ wr2, const float* __restrict__ br2) {
    __shared__ float sh1[8 * C1];
    int tid = threadIdx.x;
    int w = tid >> 5;
    int lane = tid & 31;
    int n0 = blockIdx.x * 8;
    int n = n0 + w;
    int slot = lane >> 4;
    int c = (lane & 15) * 8;        // channel base, 8 channels per lane
    {
        float4 atf0 = *(const float4*)(att + c);
        float4 atf1 = *(const float4*)(att + c + 4);
        float4 xrf0 = *(const float4*)(g_xr1 + n * C1 + c);
        float4 xrf1 = *(const float4*)(g_xr1 + n * C1 + c + 4);
        const __half2 at0 = __floats2half2_rn(atf0.x, atf0.y);
        const __half2 at1 = __floats2half2_rn(atf0.z, atf0.w);
        const __half2 at2 = __floats2half2_rn(atf1.x, atf1.y);
        const __half2 at3 = __floats2half2_rn(atf1.z, atf1.w);
        const __half2 xr0 = __floats2half2_rn(xrf0.x, xrf0.y);
        const __half2 xr1 = __floats2half2_rn(xrf0.z, xrf0.w);
        const __half2 xr2 = __floats2half2_rn(xrf1.x, xrf1.y);
        const __half2 xr3 = __floats2half2_rn(xrf1.z, xrf1.w);
        const __half2 hz  = __float2half2_rn(0.f);
        const __half2 hsl = __float2half2_rn(SLOPE);
        float a0 = 0.f, a1 = 0.f, a2 = 0.f, a3 = 0.f;
        float a4 = 0.f, a5 = 0.f, a6 = 0.f, a7 = 0.f;
        float dn = 0.f;

        int start = g_rowstart[n], end = g_rowstart[n + 1];
        int ibase = start - 1 + slot;   // virtual list: [self] + edges, slot-strided by 2

        auto ldsrc = [&](int t) -> uint4 {
            int i = ibase + 2 * t;
            int s = (i < start) ? n : ((i < end) ? g_srcs[i] : n);
            return *(const uint4*)(g_xl1h + s * C1 + c);   // 16 B/lane
        };
        auto edge = [&](uint4 u, bool valid) {
            __half2 x0 = *(__half2*)&u.x;
            __half2 x1 = *(__half2*)&u.y;
            __half2 x2 = *(__half2*)&u.z;
            __half2 x3 = *(__half2*)&u.w;
            __half2 s0 = __hadd2(x0, xr0), s1 = __hadd2(x1, xr1);
            __half2 s2 = __hadd2(x2, xr2), s3 = __hadd2(x3, xr3);
            __half2 l0 = __hfma2(hsl, __hmin2(s0, hz), __hmax2(s0, hz));   // leaky-relu
            __half2 l1 = __hfma2(hsl, __hmin2(s1, hz), __hmax2(s1, hz));
            __half2 l2 = __hfma2(hsl, __hmin2(s2, hz), __hmax2(s2, hz));
            __half2 l3 = __hfma2(hsl, __hmin2(s3, hz), __hmax2(s3, hz));
            __half2 d  = __hmul2(l0, at0);
            d = __hfma2(l1, at1, d);
            d = __hfma2(l2, at2, d);
            d = __hfma2(l3, at3, d);
            float2 df = __half22float2(d);
            float p = df.x + df.y;
            p += __shfl_xor_sync(0xffffffffu, p, 1);   // pair-sum -> full head logit
            float a = valid ? __expf(p) : 0.f;          // shift-invariant softmax
            dn += a;
            float2 f0 = __half22float2(x0), f1 = __half22float2(x1);
            float2 f2 = __half22float2(x2), f3 = __half22float2(x3);
            a0 = fmaf(a, f0.x, a0); a1 = fmaf(a, f0.y, a1);
            a2 = fmaf(a, f1.x, a2); a3 = fmaf(a, f1.y, a3);
            a4 = fmaf(a, f2.x, a4); a5 = fmaf(a, f2.y, a5);
            a6 = fmaf(a, f3.x, a6); a7 = fmaf(a, f3.y, a7);
        };

        int T = (end - start + 2) >> 1;   // ceil((len+1)/2), warp-uniform
        if (T == 1) {
            edge(ldsrc(0), ibase < end);
        } else {
            uint4 c0 = ldsrc(0), c1 = ldsrc(1);
            for (int t = 2; t < T; t++) {
                uint4 nx = ldsrc(t);      // 2 loads in flight past current edge
                edge(c0, ibase + 2 * (t - 2) < end);
                c0 = c1; c1 = nx;
            }
            edge(c0, ibase + 2 * (T - 2) < end);
            edge(c1, ibase + 2 * (T - 1) < end);
        }

        // combine the two slots (lane l <-> l^16 hold the same channels)
        a0 += __shfl_xor_sync(0xffffffffu, a0, 16);
        a1 += __shfl_xor_sync(0xffffffffu, a1, 16);
        a2 += __shfl_xor_sync(0xffffffffu, a2, 16);
        a3 += __shfl_xor_sync(0xffffffffu, a3, 16);
        a4 += __shfl_xor_sync(0xffffffffu, a4, 16);
        a5 += __shfl_xor_sync(0xffffffffu, a5, 16);
        a6 += __shfl_xor_sync(0xffffffffu, a6, 16);
        a7 += __shfl_xor_sync(0xffffffffu, a7, 16);
        dn += __shfl_xor_sync(0xffffffffu, dn, 16);

        if (slot == 0) {
            float inv = 1.f / (dn + 1e-16f);
            float4 b0 = *(const float4*)(bias + c);
            float4 b1 = *(const float4*)(bias + c + 4);
            float4 o0, o1;
            o0.x = elu1(fmaf(a0, inv, b0.x));
            o0.y = elu1(fmaf(a1, inv, b0.y));
            o0.z = elu1(fmaf(a2, inv, b0.z));
            o0.w = elu1(fmaf(a3, inv, b0.w));
            o1.x = elu1(fmaf(a4, inv, b1.x));
            o1.y = elu1(fmaf(a5, inv, b1.y));
            o1.z = elu1(fmaf(a6, inv, b1.z));
            o1.w = elu1(fmaf(a7, inv, b1.w));
            *(float4*)(sh1 + w * C1 + c) = o0;
            *(float4*)(sh1 + w * C1 + c + 4) = o1;
        }
    }
    __syncthreads();

    // Phase B: layer-2 transforms for this block's 8 nodes (h1 lives in smem)
    int idx = tid & 127;
    int half = tid >> 7;            // 0 -> xl2, 1 -> xr2
    int nl = idx >> 4, k = idx & 15;
    const float* hr = sh1 + nl * C1;
    const float* wmat = half ? wr2 : wl2;
    float s = half ? br2[k] : bl2[k];
#pragma unroll 8
    for (int j = 0; j < C1; j++) s = fmaf(hr[j], wmat[j * HID + k], s);
    int tt = (n0 + nl) * HID + k;
    if (half) g_xr2[tt] = s;
    else      g_xl2h[tt] = __float2half(s);
}

// ---------------- layer 2 gather + fused mean-pool + last-block MLP ----------
// lane layout: slot = lane>>2 (8 parallel edges), cg = (lane&3)*4 (channel base).
__global__ void gat2_mlp(const float* __restrict__ att2, const float* __restrict__ bias2,
                         const int* __restrict__ batch,
                         const float* __restrict__ w1, const float* __restrict__ b1,
                         const float* __restrict__ w2, const float* __restrict__ b2,
                         const float* __restrict__ w3, const float* __restrict__ b3,
                         float* __restrict__ out) {
    int warp = (blockIdx.x * blockDim.x + threadIdx.x) >> 5;
    int lane = threadIdx.x & 31;
    if (warp < NN) {
        int n = warp;
        int slot = lane >> 2;
        int cg = (lane & 3) * 4;
        float4 at = *(const float4*)(att2 + cg);
        float4 xr = *(const float4*)(g_xr2 + n * HID + cg);
        float4 acc = make_float4(0.f, 0.f, 0.f, 0.f);
        float dn = 0.f;

        auto ldxl2 = [&](int src) -> float4 {
            uint2 u = *(const uint2*)(g_xl2h + src * HID + cg);
            __half2 h0 = *(__half2*)&u.x;
            __half2 h1 = *(__half2*)&u.y;
            float2 f0 = __half22float2(h0);
            float2 f1 = __half22float2(h1);
            return make_float4(f0.x, f0.y, f1.x, f1.y);
        };

        int start = g_rowstart[n], end = g_rowstart[n + 1];
        // virtual list: [self] + edges, 8 per iteration
        for (int base = start - 1 + slot; base - slot < end; base += 8) {
            int idx = base;
            bool valid = idx < end;
            int src = (!valid || idx < start) ? n : g_srcs[idx];
            float4 xl = ldxl2(src);
            float p;
            p = at.x * lrelu(xl.x + xr.x);
            p = fmaf(at.y, lrelu(xl.y + xr.y), p);
            p = fmaf(at.z, lrelu(xl.z + xr.z), p);
            p = fmaf(at.w, lrelu(xl.w + xr.w), p);
            p += __shfl_xor_sync(0xffffffffu, p, 1);
            p += __shfl_xor_sync(0xffffffffu, p, 2);   // full 16-ch logit for this edge
            float a = valid ? __expf(p) : 0.f;
            dn += a;
            acc.x = fmaf(a, xl.x, acc.x);
            acc.y = fmaf(a, xl.y, acc.y);
            acc.z = fmaf(a, xl.z, acc.z);
            acc.w = fmaf(a, xl.w, acc.w);
        }
#pragma unroll
        for (int off = 4; off < 32; off <<= 1) {
            acc.x += __shfl_xor_sync(0xffffffffu, acc.x, off);
            acc.y += __shfl_xor_sync(0xffffffffu, acc.y, off);
            acc.z += __shfl_xor_sync(0xffffffffu, acc.z, off);
            acc.w += __shfl_xor_sync(0xffffffffu, acc.w, off);
            dn    += __shfl_xor_sync(0xffffffffu, dn,    off);
        }
        if (slot == 0) {
            float inv = 1.f / (dn + 1e-16f);
            float4 b = *(const float4*)(bias2 + cg);
            float4 o;
            o.x = elu1(fmaf(acc.x, inv, b.x));
            o.y = elu1(fmaf(acc.y, inv, b.y));
            o.z = elu1(fmaf(acc.z, inv, b.z));
            o.w = elu1(fmaf(acc.w, inv, b.w));
            int g = batch[n];
            float* p = g_pool + g * HID + cg;
            atomicAdd(p + 0, o.x);
            atomicAdd(p + 1, o.y);
            atomicAdd(p + 2, o.z);
            atomicAdd(p + 3, o.w);
            if (lane == 0) atomicAdd(&g_cnt[g], 1.f);
        }
    }

    // ---- last-block runs the MLP (threadFenceReduction pattern) ----
    __shared__ bool amLast;
    __syncthreads();
    if (threadIdx.x == 0) {
        __threadfence();
        unsigned tk = atomicAdd(&g_ticket, 1u);
        amLast = (tk == gridDim.x - 1);
    }
    __syncthreads();
    if (amLast) {
        if (threadIdx.x == 0) g_ticket = 0;   // reset for next replay
        int g = threadIdx.x;                  // 256 threads = BG graphs
        float cnt = fmaxf(g_cnt[g], 1.f);
        float h[HID];
#pragma unroll
        for (int k = 0; k < HID; k++) h[k] = g_pool[g * HID + k] / cnt;
        float t1[2 * HID];
#pragma unroll
        for (int j = 0; j < 2 * HID; j++) {
            float s = b1[j];
#pragma unroll
            for (int k = 0; k < HID; k++) s = fmaf(h[k], w1[k * 2 * HID + j], s);
            t1[j] = elu1(s);
        }
        float t2[HID];
#pragma unroll
        for (int k = 0; k < HID; k++) {
            float s = b2[k];
#pragma unroll
            for (int j = 0; j < 2 * HID; j++) s = fmaf(t1[j], w2[j * HID + k], s);
            t2[k] = elu1(s);
        }
#pragma unroll
        for (int o = 0; o < OUTC; o++) {
            float s = b3[o];
#pragma unroll
            for (int k = 0; k < HID; k++) s = fmaf(t2[k], w3[k * OUTC + o], s);
            out[g * OUTC + o] = s;
        }
    }
}

// ---------------- launch -----------------------------------------------------
extern "C" void kernel_launch(void* const* d_in, const int* in_sizes, int n_in,
                              void* d_out, int out_size) {
    const float* x    = (const float*)d_in[0];
    const int*   ei   = (const int*)  d_in[1];
    const int*   batch= (const int*)  d_in[2];
    const float* wl1  = (const float*)d_in[3];
    const float* bl1  = (const float*)d_in[4];
    const float* wr1  = (const float*)d_in[5];
    const float* br1  = (const float*)d_in[6];
    const float* att1 = (const float*)d_in[7];
    const float* bias1= (const float*)d_in[8];
    const float* wl2  = (const float*)d_in[9];
    const float* bl2  = (const float*)d_in[10];
    const float* wr2  = (const float*)d_in[11];
    const float* br2  = (const float*)d_in[12];
    const float* att2 = (const float*)d_in[13];
    const float* bias2= (const float*)d_in[14];
    const float* w_m1 = (const float*)d_in[15];
    const float* b_m1 = (const float*)d_in[16];
    const float* w_m2 = (const float*)d_in[17];
    const float* b_m2 = (const float*)d_in[18];
    const float* w_m3 = (const float*)d_in[19];
    const float* b_m3 = (const float*)d_in[20];
    float* out = (float*)d_out;

    const int TB = 256;

    // side stream + events, created once on the first (uncaptured) call
    static cudaStream_t s2 = nullptr;
    static cudaEvent_t evA = nullptr, evB = nullptr, evScan = nullptr, evC = nullptr;
    if (s2 == nullptr) {
        cudaStreamCreateWithFlags(&s2, cudaStreamNonBlocking);
        cudaEventCreateWithFlags(&evA, cudaEventDisableTiming);
        cudaEventCreateWithFlags(&evB, cudaEventDisableTiming);
        cudaEventCreateWithFlags(&evScan, cudaEventDisableTiming);
        cudaEventCreateWithFlags(&evC, cudaEventDisableTiming);
    }

    // fork: transform1 + pool zeroing overlap the CSR build chain
    cudaEventRecord(evA, 0);
    cudaStreamWaitEvent(s2, evA, 0);
    transform1_tiled<<<NN / 16, C1, 0, s2>>>(x, wl1, bl1, wr1, br1);
    zero_poolcnt<<<(BG * HID + TB - 1) / TB, TB, 0, s2>>>();
    cudaEventRecord(evB, s2);

    // CSR chain (g_count zero at entry; tail-zeroed off-path each call)
    csr_hist<<<(EE / 4 + TB - 1) / TB, TB>>>(ei);
    scan_fused<<<SCAN_BLOCKS, 256>>>();
    cudaEventRecord(evScan, 0);
    csr_fill<<<(EE / 4 + TB - 1) / TB, TB>>>(ei);

    // tail-zero g_count + scan flag for the next call, off the critical path
    cudaStreamWaitEvent(s2, evScan, 0);
    zero_count<<<(NN + TB - 1) / TB, TB, 0, s2>>>();
    cudaEventRecord(evC, s2);

    cudaStreamWaitEvent(0, evB, 0);   // join branch 1 before gat1 consumes xl1/xr1

    gat1_fused<<<NN / 8, 256>>>(att1, bias1, wl2, bl2, wr2, br2);

    cudaStreamWaitEvent(0, evC, 0);   // join branch 2 before capture ends
    gat2_mlp<<<(NN * 32 + TB - 1) / TB, TB>>>(att2, bias2, batch,
                                              w_m1, b_m1, w_m2, b_m2, w_m3, b_m3, out);
}

// round 16
// speedup vs baseline: 1.0436x; 1.0436x over previous
#include <cuda_runtime.h>
#include <cuda_fp16.h>
#include <math.h>

// Problem constants (match reference)
#define NN   50000
#define EE   1600000
#define INC  64
#define HID  16
#define HEADS 8
#define C1   (HEADS * HID)  // 128
#define OUTC 32
#define BG   256
#define SLOPE 0.2f
#define SCAN_BLOCKS ((NN + 255) / 256)   // 196

// ---------------- scratch (device globals; no allocation allowed) ------------
__device__ __align__(16) __half g_xl1h[NN * C1];   // fp16 source-transform (layer 1)
__device__ __align__(16) float g_xr1[NN * C1];
__device__ __align__(16) float g_out1[NN * C1];    // h1 after gat1_gather
__device__ __align__(16) __half g_xl2h[NN * HID];  // fp16 source-transform (layer 2)
__device__ __align__(16) float g_xr2[NN * HID];
__device__ __align__(16) float g_pool[BG * HID];
__device__ float g_cnt[BG];
// CSR scratch. g_count is ZERO at entry: zero-initialized at load, and tail-zeroed
// by zero_count at the end of every call (deterministic across replays).
__device__ int g_count[NN];
__device__ int g_cursor[NN];
__device__ int g_rowstart[NN + 1];
__device__ int g_srcs[EE];
__device__ int g_bsum[SCAN_BLOCKS];
__device__ int g_scanflag;        // reset by zero_count each call

__device__ __forceinline__ float elu1(float v) { return v > 0.f ? v : (__expf(v) - 1.f); }
__device__ __forceinline__ float lrelu(float v) { return v > 0.f ? v : SLOPE * v; }

// ---------------- zero helpers ------------------------------------------------
__global__ void zero_poolcnt() {
    int i = blockIdx.x * blockDim.x + threadIdx.x;
    if (i < BG * HID) g_pool[i] = 0.f;
    if (i < BG) g_cnt[i] = 0.f;
}

__global__ void zero_count() {       // tail: reset histogram + scan flag for NEXT call
    int i = blockIdx.x * blockDim.x + threadIdx.x;
    if (i < NN) g_count[i] = 0;
    if (i == 0) g_scanflag = 0;
}

// ---------------- CSR build: histogram (4 edges/thread, int4) ----------------
__global__ void csr_hist(const int* __restrict__ ei) {
    int t = blockIdx.x * blockDim.x + threadIdx.x;
    if (t * 4 >= EE) return;
    int4 d = ((const int4*)(ei + EE))[t];
    atomicAdd(&g_count[d.x], 1);
    atomicAdd(&g_count[d.y], 1);
    atomicAdd(&g_count[d.z], 1);
    atomicAdd(&g_count[d.w], 1);
}

// ---------------- single-kernel scan (flag-synced two phases) ----------------
// 196 blocks all resident in wave 1 (far under occupancy limits) -> spin is safe.
__global__ void scan_fused() {
    __shared__ int sh[256];
    __shared__ int bs[256];
    int t = threadIdx.x, bid = blockIdx.x;
    int i = bid * 256 + t;
    int v = (i < NN) ? g_count[i] : 0;
    sh[t] = v;
    __syncthreads();
    for (int off = 1; off < 256; off <<= 1) {
        int u = (t >= off) ? sh[t - off] : 0;
        __syncthreads();
        sh[t] += u;
        __syncthreads();
    }
    if (t == 0) {
        g_bsum[bid] = sh[255];
        __threadfence();
        atomicAdd(&g_scanflag, 1);
        while (atomicAdd(&g_scanflag, 0) < SCAN_BLOCKS) { }   // wait for all blocks
    }
    __syncthreads();
    bs[t] = (t < SCAN_BLOCKS) ? g_bsum[t] : 0;
    __syncthreads();
    for (int off = 1; off < 256; off <<= 1) {
        int u = (t >= off) ? bs[t - off] : 0;
        __syncthreads();
        bs[t] += u;
        __syncthreads();
    }
    int blockpref = (bid == 0) ? 0 : bs[bid - 1];
    int excl = sh[t] - v + blockpref;
    if (i < NN) { g_rowstart[i] = excl; g_cursor[i] = excl; }
    if (i == NN - 1) g_rowstart[NN] = excl + v;
}

// ---------------- CSR fill (4 edges/thread, int4) ----------------------------
__global__ void csr_fill(const int* __restrict__ ei) {
    int t = blockIdx.x * blockDim.x + threadIdx.x;
    if (t * 4 >= EE) return;
    int4 s = ((const int4*)ei)[t];
    int4 d = ((const int4*)(ei + EE))[t];
    g_srcs[atomicAdd(&g_cursor[d.x], 1)] = s.x;
    g_srcs[atomicAdd(&g_cursor[d.y], 1)] = s.y;
    g_srcs[atomicAdd(&g_cursor[d.z], 1)] = s.z;
    g_srcs[atomicAdd(&g_cursor[d.w], 1)] = s.w;
}

// ---------------- layer 1: node transforms, 16 nodes per block ---------------
__global__ void transform1_tiled(const float* __restrict__ x,
                                 const float* __restrict__ wl, const float* __restrict__ bl,
                                 const float* __restrict__ wr, const float* __restrict__ br) {
    __shared__ float sx[16 * INC];
    int j = threadIdx.x;            // output channel 0..127
    int n0 = blockIdx.x * 16;
    const float* xb = x + n0 * INC;
#pragma unroll
    for (int i = 0; i < 8; i++) sx[j + i * 128] = xb[j + i * 128];
    __syncthreads();
    float blv = bl[j], brv = br[j];
    float sl[16], sr[16];
#pragma unroll
    for (int t = 0; t < 16; t++) { sl[t] = blv; sr[t] = brv; }
#pragma unroll 4
    for (int k = 0; k < INC; k++) {
        float wlv = wl[k * C1 + j];
        float wrv = wr[k * C1 + j];
#pragma unroll
        for (int t = 0; t < 16; t++) {
            float xv = sx[t * INC + k];
            sl[t] = fmaf(xv, wlv, sl[t]);
            sr[t] = fmaf(xv, wrv, sr[t]);
        }
    }
#pragma unroll
    for (int t = 0; t < 16; t++) {
        g_xl1h[(n0 + t) * C1 + j] = __float2half(sl[t]);
        g_xr1[(n0 + t) * C1 + j] = sr[t];
    }
}

// ---------------- layer 1: warp-per-node gather, 2 slots x 16 lanes ----------
// slot = lane>>4 (2 edges in flight per warp); lane owns 8 channels (uint4 fp16).
// Softmax normalization is linear per dst: out = (sum a*xl_src)/(sum a).
__global__ void gat1_gather(const float* __restrict__ att, const float* __restrict__ bias) {
    int warp = (blockIdx.x * blockDim.x + threadIdx.x) >> 5;
    if (warp >= NN) return;
    int lane = threadIdx.x & 31;
    int n = warp;
    int slot = lane >> 4;
    int c = (lane & 15) * 8;        // channel base, 8 channels per lane
    float4 atf0 = *(const float4*)(att + c);
    float4 atf1 = *(const float4*)(att + c + 4);
    float4 xrf0 = *(const float4*)(g_xr1 + n * C1 + c);
    float4 xrf1 = *(const float4*)(g_xr1 + n * C1 + c + 4);
    const __half2 at0 = __floats2half2_rn(atf0.x, atf0.y);
    const __half2 at1 = __floats2half2_rn(atf0.z, atf0.w);
    const __half2 at2 = __floats2half2_rn(atf1.x, atf1.y);
    const __half2 at3 = __floats2half2_rn(atf1.z, atf1.w);
    const __half2 xr0 = __floats2half2_rn(xrf0.x, xrf0.y);
    const __half2 xr1 = __floats2half2_rn(xrf0.z, xrf0.w);
    const __half2 xr2 = __floats2half2_rn(xrf1.x, xrf1.y);
    const __half2 xr3 = __floats2half2_rn(xrf1.z, xrf1.w);
    const __half2 hz  = __float2half2_rn(0.f);
    const __half2 hsl = __float2half2_rn(SLOPE);
    float a0 = 0.f, a1 = 0.f, a2 = 0.f, a3 = 0.f;
    float a4 = 0.f, a5 = 0.f, a6 = 0.f, a7 = 0.f;
    float dn = 0.f;

    int start = g_rowstart[n], end = g_rowstart[n + 1];
    int ibase = start - 1 + slot;   // virtual list: [self] + edges, slot-strided by 2

    auto ldsrc = [&](int t) -> uint4 {
        int i = ibase + 2 * t;
        int s = (i < start) ? n : ((i < end) ? g_srcs[i] : n);
        return *(const uint4*)(g_xl1h + s * C1 + c);   // 16 B/lane
    };
    auto edge = [&](uint4 u, bool valid) {
        __half2 x0 = *(__half2*)&u.x;
        __half2 x1 = *(__half2*)&u.y;
        __half2 x2 = *(__half2*)&u.z;
        __half2 x3 = *(__half2*)&u.w;
        __half2 s0 = __hadd2(x0, xr0), s1 = __hadd2(x1, xr1);
        __half2 s2 = __hadd2(x2, xr2), s3 = __hadd2(x3, xr3);
        __half2 l0 = __hfma2(hsl, __hmin2(s0, hz), __hmax2(s0, hz));   // leaky-relu
        __half2 l1 = __hfma2(hsl, __hmin2(s1, hz), __hmax2(s1, hz));
        __half2 l2 = __hfma2(hsl, __hmin2(s2, hz), __hmax2(s2, hz));
        __half2 l3 = __hfma2(hsl, __hmin2(s3, hz), __hmax2(s3, hz));
        __half2 d  = __hmul2(l0, at0);
        d = __hfma2(l1, at1, d);
        d = __hfma2(l2, at2, d);
        d = __hfma2(l3, at3, d);
        float2 df = __half22float2(d);
        float p = df.x + df.y;
        p += __shfl_xor_sync(0xffffffffu, p, 1);   // pair-sum -> full head logit
        float a = valid ? __expf(p) : 0.f;          // shift-invariant softmax
        dn += a;
        float2 f0 = __half22float2(x0), f1 = __half22float2(x1);
        float2 f2 = __half22float2(x2), f3 = __half22float2(x3);
        a0 = fmaf(a, f0.x, a0); a1 = fmaf(a, f0.y, a1);
        a2 = fmaf(a, f1.x, a2); a3 = fmaf(a, f1.y, a3);
        a4 = fmaf(a, f2.x, a4); a5 = fmaf(a, f2.y, a5);
        a6 = fmaf(a, f3.x, a6); a7 = fmaf(a, f3.y, a7);
    };

    int T = (end - start + 2) >> 1;   // ceil((len+1)/2), warp-uniform
    if (T == 1) {
        edge(ldsrc(0), ibase < end);
    } else {
        uint4 c0 = ldsrc(0), c1 = ldsrc(1);
        for (int t = 2; t < T; t++) {
            uint4 nx = ldsrc(t);      // 2 loads in flight past current edge
            edge(c0, ibase + 2 * (t - 2) < end);
            c0 = c1; c1 = nx;
        }
        edge(c0, ibase + 2 * (T - 2) < end);
        edge(c1, ibase + 2 * (T - 1) < end);
    }

    // combine the two slots (lane l <-> l^16 hold the same channels)
    a0 += __shfl_xor_sync(0xffffffffu, a0, 16);
    a1 += __shfl_xor_sync(0xffffffffu, a1, 16);
    a2 += __shfl_xor_sync(0xffffffffu, a2, 16);
    a3 += __shfl_xor_sync(0xffffffffu, a3, 16);
    a4 += __shfl_xor_sync(0xffffffffu, a4, 16);
    a5 += __shfl_xor_sync(0xffffffffu, a5, 16);
    a6 += __shfl_xor_sync(0xffffffffu, a6, 16);
    a7 += __shfl_xor_sync(0xffffffffu, a7, 16);
    dn += __shfl_xor_sync(0xffffffffu, dn, 16);

    if (slot == 0) {
        float inv = 1.f / (dn + 1e-16f);
        float4 b0 = *(const float4*)(bias + c);
        float4 b1 = *(const float4*)(bias + c + 4);
        float4 o0, o1;
        o0.x = elu1(fmaf(a0, inv, b0.x));
        o0.y = elu1(fmaf(a1, inv, b0.y));
        o0.z = elu1(fmaf(a2, inv, b0.z));
        o0.w = elu1(fmaf(a3, inv, b0.w));
        o1.x = elu1(fmaf(a4, inv, b1.x));
        o1.y = elu1(fmaf(a5, inv, b1.y));
        o1.z = elu1(fmaf(a6, inv, b1.z));
        o1.w = elu1(fmaf(a7, inv, b1.w));
        *(float4*)(g_out1 + n * C1 + c) = o0;
        *(float4*)(g_out1 + n * C1 + c + 4) = o1;
    }
}

// ---------------- layer 2: node transforms, tiled (16 nodes / 256 thr) -------
__global__ void transform2_tiled(const float* __restrict__ wl, const float* __restrict__ bl,
                                 const float* __restrict__ wr, const float* __restrict__ br) {
    __shared__ float sh[16 * C1];
    int tid = threadIdx.x;          // 256
    int n0 = blockIdx.x * 16;
    const float4* src = (const float4*)(g_out1 + n0 * C1);
    float4* dst = (float4*)sh;
    dst[tid] = src[tid];
    dst[tid + 256] = src[tid + 256];
    __syncthreads();
    int nl = tid >> 4;              // node local 0..15
    int k = tid & 15;               // out channel 0..15
    const float* hr = sh + nl * C1;
    float sl = bl[k], sr = br[k];
#pragma unroll 8
    for (int j = 0; j < C1; j++) {
        float hv = hr[j];
        sl = fmaf(hv, wl[j * HID + k], sl);
        sr = fmaf(hv, wr[j * HID + k], sr);
    }
    int t = (n0 + nl) * HID + k;
    g_xl2h[t] = __float2half(sl);
    g_xr2[t] = sr;
}

// ---------------- layer 2: warp-per-node gather + fused mean-pool ------------
// lane layout: slot = lane>>2 (8 parallel edges), cg = (lane&3)*4 (channel base).
__global__ void gat2_gather(const float* __restrict__ att2, const float* __restrict__ bias2,
                            const int* __restrict__ batch) {
    int warp = (blockIdx.x * blockDim.x + threadIdx.x) >> 5;
    if (warp >= NN) return;
    int lane = threadIdx.x & 31;
    int n = warp;
    int slot = lane >> 2;
    int cg = (lane & 3) * 4;
    float4 at = *(const float4*)(att2 + cg);
    float4 xr = *(const float4*)(g_xr2 + n * HID + cg);
    float4 acc = make_float4(0.f, 0.f, 0.f, 0.f);
    float dn = 0.f;

    auto ldxl2 = [&](int src) -> float4 {
        uint2 u = *(const uint2*)(g_xl2h + src * HID + cg);
        __half2 h0 = *(__half2*)&u.x;
        __half2 h1 = *(__half2*)&u.y;
        float2 f0 = __half22float2(h0);
        float2 f1 = __half22float2(h1);
        return make_float4(f0.x, f0.y, f1.x, f1.y);
    };

    int start = g_rowstart[n], end = g_rowstart[n + 1];
    // virtual list: [self] + edges, 8 per iteration
    for (int base = start - 1 + slot; base - slot < end; base += 8) {
        int idx = base;
        bool valid = idx < end;
        int src = (!valid || idx < start) ? n : g_srcs[idx];
        float4 xl = ldxl2(src);
        float p;
        p = at.x * lrelu(xl.x + xr.x);
        p = fmaf(at.y, lrelu(xl.y + xr.y), p);
        p = fmaf(at.z, lrelu(xl.z + xr.z), p);
        p = fmaf(at.w, lrelu(xl.w + xr.w), p);
        p += __shfl_xor_sync(0xffffffffu, p, 1);
        p += __shfl_xor_sync(0xffffffffu, p, 2);   // full 16-ch logit for this edge
        float a = valid ? __expf(p) : 0.f;
        dn += a;
        acc.x = fmaf(a, xl.x, acc.x);
        acc.y = fmaf(a, xl.y, acc.y);
        acc.z = fmaf(a, xl.z, acc.z);
        acc.w = fmaf(a, xl.w, acc.w);
    }
    // reduce across the 8 slots
#pragma unroll
    for (int off = 4; off < 32; off <<= 1) {
        acc.x += __shfl_xor_sync(0xffffffffu, acc.x, off);
        acc.y += __shfl_xor_sync(0xffffffffu, acc.y, off);
        acc.z += __shfl_xor_sync(0xffffffffu, acc.z, off);
        acc.w += __shfl_xor_sync(0xffffffffu, acc.w, off);
        dn    += __shfl_xor_sync(0xffffffffu, dn,    off);
    }
    if (slot == 0) {
        float inv = 1.f / (dn + 1e-16f);
        float4 b = *(const float4*)(bias2 + cg);
        float4 o;
        o.x = elu1(fmaf(acc.x, inv, b.x));
        o.y = elu1(fmaf(acc.y, inv, b.y));
        o.z = elu1(fmaf(acc.z, inv, b.z));
        o.w = elu1(fmaf(acc.w, inv, b.w));
        int g = batch[n];
        float* p = g_pool + g * HID + cg;
        atomicAdd(p + 0, o.x);
        atomicAdd(p + 1, o.y);
        atomicAdd(p + 2, o.z);
        atomicAdd(p + 3, o.w);
        if (lane == 0) atomicAdd(&g_cnt[g], 1.f);
    }
}

// ---------------- mean + MLP -------------------------------------------------
__global__ void mlp_kernel(const float* __restrict__ w1, const float* __restrict__ b1,
                           const float* __restrict__ w2, const float* __restrict__ b2,
                           const float* __restrict__ w3, const float* __restrict__ b3,
                           float* __restrict__ out) {
    int g = blockIdx.x * blockDim.x + threadIdx.x;
    if (g >= BG) return;
    float cnt = fmaxf(g_cnt[g], 1.f);
    float h[HID];
#pragma unroll
    for (int k = 0; k < HID; k++) h[k] = g_pool[g * HID + k] / cnt;
    float t1[2 * HID];
#pragma unroll
    for (int j = 0; j < 2 * HID; j++) {
        float s = b1[j];
#pragma unroll
        for (int k = 0; k < HID; k++) s = fmaf(h[k], w1[k * 2 * HID + j], s);
        t1[j] = elu1(s);
    }
    float t2[HID];
#pragma unroll
    for (int k = 0; k < HID; k++) {
        float s = b2[k];
#pragma unroll
        for (int j = 0; j < 2 * HID; j++) s = fmaf(t1[j], w2[j * HID + k], s);
        t2[k] = elu1(s);
    }
#pragma unroll
    for (int o = 0; o < OUTC; o++) {
        float s = b3[o];
#pragma unroll
        for (int k = 0; k < HID; k++) s = fmaf(t2[k], w3[k * OUTC + o], s);
        out[g * OUTC + o] = s;
    }
}

// ---------------- launch -----------------------------------------------------
extern "C" void kernel_launch(void* const* d_in, const int* in_sizes, int n_in,
                              void* d_out, int out_size) {
    const float* x    = (const float*)d_in[0];
    const int*   ei   = (const int*)  d_in[1];
    const int*   batch= (const int*)  d_in[2];
    const float* wl1  = (const float*)d_in[3];
    const float* bl1  = (const float*)d_in[4];
    const float* wr1  = (const float*)d_in[5];
    const float* br1  = (const float*)d_in[6];
    const float* att1 = (const float*)d_in[7];
    const float* bias1= (const float*)d_in[8];
    const float* wl2  = (const float*)d_in[9];
    const float* bl2  = (const float*)d_in[10];
    const float* wr2  = (const float*)d_in[11];
    const float* br2  = (const float*)d_in[12];
    const float* att2 = (const float*)d_in[13];
    const float* bias2= (const float*)d_in[14];
    const float* w_m1 = (const float*)d_in[15];
    const float* b_m1 = (const float*)d_in[16];
    const float* w_m2 = (const float*)d_in[17];
    const float* b_m2 = (const float*)d_in[18];
    const float* w_m3 = (const float*)d_in[19];
    const float* b_m3 = (const float*)d_in[20];
    float* out = (float*)d_out;

    const int TB = 256;

    // side stream + events, created once on the first (uncaptured) call
    static cudaStream_t s2 = nullptr;
    static cudaEvent_t evA = nullptr, evB = nullptr, evScan = nullptr, evC = nullptr;
    if (s2 == nullptr) {
        cudaStreamCreateWithFlags(&s2, cudaStreamNonBlocking);
        cudaEventCreateWithFlags(&evA, cudaEventDisableTiming);
        cudaEventCreateWithFlags(&evB, cudaEventDisableTiming);
        cudaEventCreateWithFlags(&evScan, cudaEventDisableTiming);
        cudaEventCreateWithFlags(&evC, cudaEventDisableTiming);
    }

    // fork: transform1 + pool zeroing overlap the CSR build chain
    cudaEventRecord(evA, 0);
    cudaStreamWaitEvent(s2, evA, 0);
    transform1_tiled<<<NN / 16, C1, 0, s2>>>(x, wl1, bl1, wr1, br1);
    zero_poolcnt<<<(BG * HID + TB - 1) / TB, TB, 0, s2>>>();
    cudaEventRecord(evB, s2);

    // CSR chain (g_count zero at entry; tail-zeroed off-path each call)
    csr_hist<<<(EE / 4 + TB - 1) / TB, TB>>>(ei);
    scan_fused<<<SCAN_BLOCKS, 256>>>();
    cudaEventRecord(evScan, 0);
    csr_fill<<<(EE / 4 + TB - 1) / TB, TB>>>(ei);

    // tail-zero g_count + scan flag for the next call, off the critical path
    cudaStreamWaitEvent(s2, evScan, 0);
    zero_count<<<(NN + TB - 1) / TB, TB, 0, s2>>>();
    cudaEventRecord(evC, s2);

    cudaStreamWaitEvent(0, evB, 0);   // join branch 1 before gat1 consumes xl1/xr1

    gat1_gather<<<(NN * 32 + TB - 1) / TB, TB>>>(att1, bias1);
    transform2_tiled<<<NN / 16, 256>>>(wl2, bl2, wr2, br2);
    gat2_gather<<<(NN * 32 + TB - 1) / TB, TB>>>(att2, bias2, batch);

    cudaStreamWaitEvent(0, evC, 0);   // join branch 2 before capture ends
    mlp_kernel<<<1, BG>>>(w_m1, b_m1, w_m2, b_m2, w_m3, b_m3, out);
}